// round 9
// baseline (speedup 1.0000x reference)
#include <cuda_runtime.h>
#include <cuda_bf16.h>

// Problem constants
#define NPART    148     // persistent CTAs (one per SM)
#define NCHUNK1  8192    // K1: chunks of 32 points  (262144/32);  b = chunk>>11
#define NCHUNK3  4096    // K3: chunks of 64 points  (262144/64);  b = chunk>>10

// Deterministic scratch (no cudaMalloc allowed)
__device__ float g_part[4 * NPART * 4096];   // per-CTA partial kv  [b][cta][h*1024+d*32+e]
__device__ float g_kv[4 * 4096];             // reduced kv          [b][h*1024+d*32+e]
__device__ float g_wqeff[4 * 16384];         // folded weights      [b][n*128 + c]  (n = e*4+h)

// ---- packed f32x2 helpers ----
__device__ __forceinline__ unsigned long long dup2(float x) {
    unsigned long long r;
    asm("mov.b64 %0, {%1, %1};" : "=l"(r) : "f"(x));
    return r;
}
__device__ __forceinline__ unsigned long long fma2(unsigned long long a,
                                                   unsigned long long b,
                                                   unsigned long long c) {
    unsigned long long d;
    asm("fma.rn.f32x2 %0, %1, %2, %3;" : "=l"(d) : "l"(a), "l"(b), "l"(c));
    return d;
}
__device__ __forceinline__ float2 unpk(unsigned long long a) {
    float2 f;
    asm("mov.b64 {%0, %1}, %2;" : "=f"(f.x), "=f"(f.y) : "l"(a));
    return f;
}

// ---- cp.async helpers ----
__device__ __forceinline__ void cp16(void* smem_dst, const float* gsrc) {
    unsigned s = (unsigned)__cvta_generic_to_shared(smem_dst);
    asm volatile("cp.async.cg.shared.global [%0], [%1], 16;" :: "r"(s), "l"(gsrc));
}
__device__ __forceinline__ void cp_commit() {
    asm volatile("cp.async.commit_group;");
}
__device__ __forceinline__ void cp_wait_all() {
    asm volatile("cp.async.wait_group 0;");
}
__device__ __forceinline__ void cp_wait1() {
    asm volatile("cp.async.wait_group 1;");
}

// ---- shared mma.sync infrastructure ----
// bf16 tile [rows][256 bytes], XOR-swizzled at 16B granularity.
__device__ __forceinline__ unsigned sw_off(int row, int kbyte) {
    return (unsigned)((row << 8) + (kbyte ^ ((row & 7) << 4)));
}
// fp32 staging [rows][1024 bytes], XOR-swizzled at 16B granularity.
__device__ __forceinline__ unsigned skv_off(int row, int colb) {
    return (unsigned)((row << 10) + (colb ^ ((row & 7) << 4)));
}

__device__ __forceinline__ void mma_bf16(float* c,
                                         unsigned a0, unsigned a1, unsigned a2, unsigned a3,
                                         unsigned b0, unsigned b1) {
    asm volatile(
        "mma.sync.aligned.m16n8k16.row.col.f32.bf16.bf16.f32 "
        "{%0,%1,%2,%3}, {%4,%5,%6,%7}, {%8,%9}, {%0,%1,%2,%3};"
        : "+f"(c[0]), "+f"(c[1]), "+f"(c[2]), "+f"(c[3])
        : "r"(a0), "r"(a1), "r"(a2), "r"(a3), "r"(b0), "r"(b1));
}

__device__ __forceinline__ void ldsm4(unsigned* r, unsigned a) {
    asm volatile("ldmatrix.sync.aligned.m8n8.x4.shared.b16 {%0,%1,%2,%3}, [%4];"
                 : "=r"(r[0]), "=r"(r[1]), "=r"(r[2]), "=r"(r[3]) : "r"(a));
}

// ============================================================================
// Kernel 1 (pipelined): X@(Wk|Wv) bf16x3 -> LN -> outer partials.
// 32-point chunks, 512 threads, 2 syncs/chunk.
// smem: WT 128K | X tiles 2x16K | sKV 2x32K | partials 2K = 231424 B
// ============================================================================
#define K1_WT_HI 0
#define K1_WT_LO 65536
#define K1_XT    131072     // buf b: hi at +b*16384, lo at +b*16384+8192
#define K1_KV    163840     // buf b: +b*32768
#define K1_PART  229376     // partk 1K | partv 1K
#define K1_SMEM  231424

// Convert 32-pt register-resident raw X -> hi/lo swizzled bf16 tiles.
__device__ __forceinline__ void cvt32(const float4* xr, char* hi, int tid) {
#pragma unroll
    for (int i = 0; i < 2; i++) {
        const int idx = tid + i * 512;
        const int row = idx >> 5;          // 0..31
        const int kb  = (idx & 31) << 3;
        const float4 x = xr[i];
        __nv_bfloat162 h0 = __floats2bfloat162_rn(x.x, x.y);
        __nv_bfloat162 h1 = __floats2bfloat162_rn(x.z, x.w);
        float2 f0 = __bfloat1622float2(h0);
        float2 f1 = __bfloat1622float2(h1);
        __nv_bfloat162 l0 = __floats2bfloat162_rn(x.x - f0.x, x.y - f0.y);
        __nv_bfloat162 l1 = __floats2bfloat162_rn(x.z - f1.x, x.w - f1.y);
        const unsigned off = sw_off(row, kb);
        *(__nv_bfloat162*)(hi + off)            = h0;
        *(__nv_bfloat162*)(hi + off + 4)        = h1;
        *(__nv_bfloat162*)(hi + 8192 + off)     = l0;
        *(__nv_bfloat162*)(hi + 8192 + off + 4) = l1;
    }
}

__global__ void __launch_bounds__(512, 1)
k1_kv_mma(const float* __restrict__ X,
          const float* __restrict__ Wk, const float* __restrict__ Wv,
          const float* __restrict__ gamma, const float* __restrict__ beta)
{
    extern __shared__ char smem[];
    char* wth = smem + K1_WT_HI;
    char* wtl = smem + K1_WT_LO;
    float2* partk = (float2*)(smem + K1_PART);
    float2* partv = (float2*)(smem + K1_PART + 1024);

    const unsigned xt_u  = (unsigned)__cvta_generic_to_shared(smem + K1_XT);
    const unsigned wth_u = (unsigned)__cvta_generic_to_shared(wth);

    const int tid  = threadIdx.x;
    const int lane = tid & 31;
    const int warp = tid >> 5;   // 16 warps
    const int qr = lane >> 2;
    const int qc = lane & 3;

    // ---- One-time: transpose + bf16-split Wk|Wv into WT tiles (256 rows) ----
    for (int idx = tid; idx < 4096; idx += 512) {
        const int c  = idx >> 5;
        const int n4 = (idx & 31) << 2;
        const float4 wk = ((const float4*)Wk)[idx];
        const float4 wv = ((const float4*)Wv)[idx];
#pragma unroll
        for (int j = 0; j < 4; j++) {
            const float vk = (&wk.x)[j];
            const float vv = (&wv.x)[j];
            __nv_bfloat16 hk = __float2bfloat16(vk);
            __nv_bfloat16 hv = __float2bfloat16(vv);
            __nv_bfloat16 lk = __float2bfloat16(vk - __bfloat162float(hk));
            __nv_bfloat16 lv = __float2bfloat16(vv - __bfloat162float(hv));
            const unsigned ok = sw_off(n4 + j,       c * 2);
            const unsigned ov = sw_off(128 + n4 + j, c * 2);
            *(__nv_bfloat16*)(wth + ok) = hk;
            *(__nv_bfloat16*)(wtl + ok) = lk;
            *(__nv_bfloat16*)(wth + ov) = hv;
            *(__nv_bfloat16*)(wtl + ov) = lv;
        }
    }

    // Warp tile: 16 rows x 32 cols.  n0g spans the full 256 (k|v) columns.
    const int m0  = (warp & 1) * 16;
    const int n0g = (warp >> 1) * 32;      // 0..224
    const int kwarp = (n0g < 128);
    const int nw = (warp >> 1) & 3;

    // gamma/beta in registers for this thread's 8 columns
    float gv[8], bv[8];
#pragma unroll
    for (int nj = 0; nj < 4; nj++)
#pragma unroll
        for (int zz = 0; zz < 2; zz++) {
            const int ch = (n0g + nj * 8 + qc * 2 + zz) & 127;
            gv[nj * 2 + zz] = gamma[ch];
            bv[nj * 2 + zz] = beta[ch];
        }

    // Outer-product entry assignment: 8 entries (4d x 2e) per thread
    const int hh   = tid >> 7;
    const int idx2 = tid & 127;
    const int d0 = (idx2 >> 4) << 2;
    const int e0 = (idx2 & 15) << 1;
    const unsigned kcb = (unsigned)((hh * 32 + d0) * 4);
    const unsigned vcb = (unsigned)(512 + (hh * 32 + e0) * 4);

    unsigned long long acc[4];
#pragma unroll
    for (int i = 0; i < 4; i++) acc[i] = 0ull;

    // ldmatrix address precompute
    const int laneK = lane & 16;
    const int bKoff = (lane & 8) << 1;
    unsigned aBase, aSw, bBase[2], bSw[2];
    {
        const int row = m0 + (lane & 15);          // 0..31
        aSw = (unsigned)((row & 7) << 4);
        aBase = xt_u + row * 256;
    }
#pragma unroll
    for (int p = 0; p < 2; p++) {
        const int row = n0g + p * 16 + ((lane >> 1) & 8) + (lane & 7);  // 0..255
        bSw[p] = (unsigned)((row & 7) << 4);
        bBase[p] = wth_u + row * 256;
    }

    // Prolog: load chunk0 raw X, convert into tile buf 0, prefetch chunk1 regs
    float4 xr[2];
    const int chunk0 = blockIdx.x;
    {
        const float4* src = (const float4*)X + (size_t)chunk0 * 1024;
        xr[0] = src[tid]; xr[1] = src[tid + 512];
        cvt32(xr, smem + K1_XT, tid);
        const int c1 = chunk0 + NPART;
        if (c1 < NCHUNK1) {
            const float4* s1 = (const float4*)X + (size_t)c1 * 1024;
            xr[0] = s1[tid]; xr[1] = s1[tid + 512];
        }
    }
    __syncthreads();

    int pend = -1, pbuf = 0, ob = -1;
    int it = 0;
    for (int chunk = chunk0; chunk < NCHUNK1; chunk += NPART, it++) {
        const int cur = it & 1;

        // ---- convert next chunk's tiles (other buffer); prefetch i+2 regs ----
        {
            const int nxt = chunk + NPART;
            if (nxt < NCHUNK1) {
                cvt32(xr, smem + K1_XT + (cur ^ 1) * 16384, tid);
                const int nxt2 = nxt + NPART;
                if (nxt2 < NCHUNK1) {
                    const float4* src = (const float4*)X + (size_t)nxt2 * 1024;
                    xr[0] = src[tid]; xr[1] = src[tid + 512];
                }
            }
        }

        // ---- MMA(i) on tiles[cur]  (bf16x3) ----
        float c[4][4];
#pragma unroll
        for (int nj = 0; nj < 4; nj++)
#pragma unroll
            for (int z = 0; z < 4; z++) c[nj][z] = 0.f;

        const unsigned bufo = (unsigned)(cur * 16384);
#pragma unroll
        for (int ks = 0; ks < 8; ks++) {
            const int kb = ks * 32;
            unsigned ah[4], al[4], bh[4][2], bl[4][2];
            {
                const unsigned off = (unsigned)(kb + laneK) ^ aSw;
                ldsm4(ah, aBase + bufo + off);
                ldsm4(al, aBase + bufo + 8192u + off);
            }
#pragma unroll
            for (int p = 0; p < 2; p++) {
                const unsigned off = (unsigned)(kb + bKoff) ^ bSw[p];
                unsigned t[4];
                ldsm4(t, bBase[p] + off);
                bh[2 * p][0] = t[0]; bh[2 * p][1] = t[1];
                bh[2 * p + 1][0] = t[2]; bh[2 * p + 1][1] = t[3];
                ldsm4(t, bBase[p] + 65536u + off);
                bl[2 * p][0] = t[0]; bl[2 * p][1] = t[1];
                bl[2 * p + 1][0] = t[2]; bl[2 * p + 1][1] = t[3];
            }
#pragma unroll
            for (int nj = 0; nj < 4; nj++) {
                mma_bf16(c[nj], ah[0], ah[1], ah[2], ah[3], bh[nj][0], bh[nj][1]);
                mma_bf16(c[nj], ah[0], ah[1], ah[2], ah[3], bl[nj][0], bl[nj][1]);
                mma_bf16(c[nj], al[0], al[1], al[2], al[3], bh[nj][0], bh[nj][1]);
            }
        }

        // ---- LN partial stats from registers ----
#pragma unroll
        for (int half = 0; half < 2; half++) {
            float s = 0.f, q = 0.f;
#pragma unroll
            for (int nj = 0; nj < 4; nj++) {
                const float v0 = c[nj][half * 2];
                const float v1 = c[nj][half * 2 + 1];
                s += v0 + v1;
                q += v0 * v0 + v1 * v1;
            }
            s += __shfl_xor_sync(0xffffffffu, s, 1);
            q += __shfl_xor_sync(0xffffffffu, q, 1);
            s += __shfl_xor_sync(0xffffffffu, s, 2);
            q += __shfl_xor_sync(0xffffffffu, q, 2);
            if (qc == 0) {
                const int row = m0 + half * 8 + qr;
                (kwarp ? partk : partv)[row * 4 + nw] = make_float2(s, q);
            }
        }

        // ---- outer product for PREVIOUS chunk (overlaps other warps' MMA) ----
        if (pend >= 0) {
            const int bj = pend >> 11;
            if (bj != ob) {
                if (ob >= 0) {
                    float* dst = g_part + ((size_t)ob * NPART + blockIdx.x) * 4096
                               + hh * 1024 + d0 * 32 + e0;
#pragma unroll
                    for (int i = 0; i < 4; i++) {
                        *(float2*)(dst + i * 32) = unpk(acc[i]);
                        acc[i] = 0ull;
                    }
                }
                ob = bj;
            }
            const char* skv = smem + K1_KV + pbuf * 32768;
#pragma unroll 8
            for (int p = 0; p < 32; p++) {
                const float4 kk = *(const float4*)(skv + skv_off(p, kcb));
                const unsigned long long vv =
                    *(const unsigned long long*)(skv + skv_off(p, vcb));
                acc[0] = fma2(vv, dup2(kk.x), acc[0]);
                acc[1] = fma2(vv, dup2(kk.y), acc[1]);
                acc[2] = fma2(vv, dup2(kk.z), acc[2]);
                acc[3] = fma2(vv, dup2(kk.w), acc[3]);
            }
        }
        __syncthreads();   // s_a: partials visible; outer(prev) done

        // ---- stats (per-warp) + normalize + store kn/vn to sKV[cur] ----
        {
            char* skv = smem + K1_KV + cur * 32768;
            const float4* pk = (const float4*)(kwarp ? partk : partv);
#pragma unroll
            for (int half = 0; half < 2; half++) {
                const int row = m0 + half * 8 + qr;
                const float4 q0 = pk[row * 2];
                const float4 q1 = pk[row * 2 + 1];
                const float s = q0.x + q0.z + q1.x + q1.z;
                const float q = q0.y + q0.w + q1.y + q1.w;
                const float mu = s * (1.f / 128.f);
                const float rr = rsqrtf(q * (1.f / 128.f) - mu * mu + 1e-5f);
                const float mm = -mu * rr;
#pragma unroll
                for (int nj = 0; nj < 4; nj++)
#pragma unroll
                    for (int zz = 0; zz < 2; zz++) {
                        float& v = c[nj][half * 2 + zz];
                        v = fmaf(fmaf(v, rr, mm), gv[nj * 2 + zz], bv[nj * 2 + zz]);
                    }
            }
#pragma unroll
            for (int nj = 0; nj < 4; nj++) {
                const int colb = (n0g + nj * 8 + qc * 2) * 4;
                *(float2*)(skv + skv_off(m0 + qr,     colb)) = make_float2(c[nj][0], c[nj][1]);
                *(float2*)(skv + skv_off(m0 + 8 + qr, colb)) = make_float2(c[nj][2], c[nj][3]);
            }
        }
        pend = chunk; pbuf = cur;
        __syncthreads();   // s_b: sKV[cur] + next tiles complete
    }

    // Epilogue: outer for the last chunk, then flush
    if (pend >= 0) {
        const int bj = pend >> 11;
        if (bj != ob) {
            if (ob >= 0) {
                float* dst = g_part + ((size_t)ob * NPART + blockIdx.x) * 4096
                           + hh * 1024 + d0 * 32 + e0;
#pragma unroll
                for (int i = 0; i < 4; i++) {
                    *(float2*)(dst + i * 32) = unpk(acc[i]);
                    acc[i] = 0ull;
                }
            }
            ob = bj;
        }
        const char* skv = smem + K1_KV + pbuf * 32768;
#pragma unroll 8
        for (int p = 0; p < 32; p++) {
            const float4 kk = *(const float4*)(skv + skv_off(p, kcb));
            const unsigned long long vv =
                *(const unsigned long long*)(skv + skv_off(p, vcb));
            acc[0] = fma2(vv, dup2(kk.x), acc[0]);
            acc[1] = fma2(vv, dup2(kk.y), acc[1]);
            acc[2] = fma2(vv, dup2(kk.z), acc[2]);
            acc[3] = fma2(vv, dup2(kk.w), acc[3]);
        }
    }
    if (ob >= 0) {
        float* dst = g_part + ((size_t)ob * NPART + blockIdx.x) * 4096
                   + hh * 1024 + d0 * 32 + e0;
#pragma unroll
        for (int i = 0; i < 4; i++)
            *(float2*)(dst + i * 32) = unpk(acc[i]);
    }
}

// ============================================================================
// Kernel 2a: reduce 148 per-CTA partials -> g_kv.
// ============================================================================
__global__ void k2a_reduce()
{
    const int gid = blockIdx.x * 256 + threadIdx.x;
    const int b = gid >> 12;
    const int e = gid & 4095;
    const float* src = g_part + (size_t)b * NPART * 4096 + e;
    float s = 0.f;
#pragma unroll 4
    for (int j = 0; j < NPART; j++) s += src[(size_t)j * 4096];
    g_kv[gid] = s;
}

// ============================================================================
// Kernel 2b: Wq_eff[b][n][c] = (1/N) * sum_d Wq[c][h*32+d] * kv[b][h][d][e]
// ============================================================================
__global__ void k2b_fold(const float* __restrict__ Wq)
{
    const int gid = blockIdx.x * 256 + threadIdx.x;
    const int b  = gid >> 14;
    const int r  = gid & 16383;
    const int cp = r >> 7;
    const int co = r & 127;
    const int e  = co >> 2;
    const int h  = co & 3;
    const float* wq = Wq + cp * 128 + h * 32;
    const float* kv = g_kv + b * 4096 + h * 1024 + e;
    float s = 0.f;
#pragma unroll
    for (int d = 0; d < 32; d++) s += wq[d] * kv[d * 32];
    g_wqeff[b * 16384 + co * 128 + cp] = s * (1.f / 65536.f);
}

// ============================================================================
// Kernel 3 (pipelined): out = X @ Wq_eff[b]^T  (bf16x3), 64-pt chunks,
// double-buffered raw (cp.async) + tiles, 1 sync per chunk.
// smem: W 64K | X tiles 2x32K | raw 2x32K = 192 KB
// ============================================================================
#define K3S_W_HI 0
#define K3S_W_LO 32768
#define K3S_XT   65536     // buf b: hi at +b*32768, lo at +b*32768+16384
#define K3S_RAW  131072    // buf b: +b*32768
#define K3_SMEM  196608

__device__ __forceinline__ void cvt64(const float* __restrict__ src,
                                      char* hi, int tid) {
#pragma unroll
    for (int i = 0; i < 4; i++) {
        const int idx = tid + i * 512;
        const int row = idx >> 5;          // 0..63
        const int kb  = (idx & 31) << 3;
        const float4 x = *(const float4*)(src + idx * 4);
        __nv_bfloat162 h0 = __floats2bfloat162_rn(x.x, x.y);
        __nv_bfloat162 h1 = __floats2bfloat162_rn(x.z, x.w);
        float2 f0 = __bfloat1622float2(h0);
        float2 f1 = __bfloat1622float2(h1);
        __nv_bfloat162 l0 = __floats2bfloat162_rn(x.x - f0.x, x.y - f0.y);
        __nv_bfloat162 l1 = __floats2bfloat162_rn(x.z - f1.x, x.w - f1.y);
        const unsigned off = sw_off(row, kb);
        *(__nv_bfloat162*)(hi + off)             = h0;
        *(__nv_bfloat162*)(hi + off + 4)         = h1;
        *(__nv_bfloat162*)(hi + 16384 + off)     = l0;
        *(__nv_bfloat162*)(hi + 16384 + off + 4) = l1;
    }
}

__device__ __forceinline__ void cvt_w512(const float* __restrict__ src,
                                         char* hi_base, char* lo_base, int tid) {
    if (tid < 256) {
#pragma unroll
        for (int i = 0; i < 16; i++) {
            const int idx = tid + i * 256;
            const int row = idx >> 5;
            const int kb  = (idx & 31) << 3;
            const float4 x = *(const float4*)(src + idx * 4);
            __nv_bfloat162 h0 = __floats2bfloat162_rn(x.x, x.y);
            __nv_bfloat162 h1 = __floats2bfloat162_rn(x.z, x.w);
            float2 f0 = __bfloat1622float2(h0);
            float2 f1 = __bfloat1622float2(h1);
            __nv_bfloat162 l0 = __floats2bfloat162_rn(x.x - f0.x, x.y - f0.y);
            __nv_bfloat162 l1 = __floats2bfloat162_rn(x.z - f1.x, x.w - f1.y);
            const unsigned off = sw_off(row, kb);
            *(__nv_bfloat162*)(hi_base + off)     = h0;
            *(__nv_bfloat162*)(hi_base + off + 4) = h1;
            *(__nv_bfloat162*)(lo_base + off)     = l0;
            *(__nv_bfloat162*)(lo_base + off + 4) = l1;
        }
    }
}

__global__ void __launch_bounds__(512, 1)
k3_out_mma(const float* __restrict__ X, float* __restrict__ out)
{
    extern __shared__ char smem[];
    const int tid  = threadIdx.x;
    const int lane = tid & 31;
    const int warp = tid >> 5;   // 16 warps

    // warp tile 16 x 32 over the 64 x 128 output
    const int m0 = (warp & 3) * 16;
    const int n0 = (warp >> 2) * 32;
    const int qr = lane >> 2;
    const int qc = lane & 3;

    const unsigned xt_u = (unsigned)__cvta_generic_to_shared(smem + K3S_XT);
    const unsigned wh_u = (unsigned)__cvta_generic_to_shared(smem + K3S_W_HI);

    const int laneK = lane & 16;
    const int bKoff = (lane & 8) << 1;
    unsigned aBase, aSw, bBase[2], bSw[2];
    {
        const int row = m0 + (lane & 15);          // 0..63
        aSw = (unsigned)((row & 7) << 4);
        aBase = xt_u + row * 256;
    }
#pragma unroll
    for (int p = 0; p < 2; p++) {
        const int row = n0 + p * 16 + ((lane >> 1) & 8) + (lane & 7);  // 0..127
        bSw[p] = (unsigned)((row & 7) << 4);
        bBase[p] = wh_u + row * 256;
    }

    float* raw0 = (float*)(smem + K3S_RAW);
    float* raw1 = (float*)(smem + K3S_RAW + 32768);

    // Prolog: stage raw0 (chunk0), raw1 (chunk0+NPART); convert W(b=0), X(chunk0)
    const int chunk0 = blockIdx.x;
    {
        const float* src = X + (size_t)chunk0 * 8192;
#pragma unroll
        for (int i = 0; i < 4; i++)
            cp16(raw0 + (tid + i * 512) * 4, src + (tid + i * 512) * 4);
        cp_commit();
        const int c1 = chunk0 + NPART;
        if (c1 < NCHUNK3) {
            const float* s1 = X + (size_t)c1 * 8192;
#pragma unroll
            for (int i = 0; i < 4; i++)
                cp16(raw1 + (tid + i * 512) * 4, s1 + (tid + i * 512) * 4);
        }
        cp_commit();
        cvt_w512(g_wqeff, smem + K3S_W_HI, smem + K3S_W_LO, tid);
        cp_wait1();                               // raw0 ready
        cvt64(raw0, smem + K3S_XT, tid);
    }
    __syncthreads();

    int cur_b = 0;
    int it = 0;
    for (int chunk = chunk0; chunk < NCHUNK3; chunk += NPART, it++) {
        const int cur = it & 1;
        const int b = chunk >> 10;
        if (b != cur_b) {
            cvt_w512(g_wqeff + b * 16384, smem + K3S_W_HI, smem + K3S_W_LO, tid);
            cur_b = b;
            __syncthreads();
        }

        // pipeline: convert next chunk's tiles, prefetch chunk i+2 raw
        {
            const int nxt = chunk + NPART;
            if (nxt < NCHUNK3) {
                cp_wait_all();                     // raw[cur^1] (chunk i+1) ready
                cvt64((cur ^ 1) ? raw1 : raw0,
                      smem + K3S_XT + (cur ^ 1) * 32768, tid);
                const int nxt2 = nxt + NPART;
                if (nxt2 < NCHUNK3) {
                    float* dst = cur ? raw1 : raw0;
                    const float* src = X + (size_t)nxt2 * 8192;
#pragma unroll
                    for (int i = 0; i < 4; i++)
                        cp16(dst + (tid + i * 512) * 4, src + (tid + i * 512) * 4);
                }
                cp_commit();
            }
        }

        // MMA(i) on tiles[cur]
        float c[4][4];
#pragma unroll
        for (int nj = 0; nj < 4; nj++)
#pragma unroll
            for (int z = 0; z < 4; z++) c[nj][z] = 0.f;

        const unsigned bufo = (unsigned)(cur * 32768);
#pragma unroll
        for (int ks = 0; ks < 8; ks++) {
            const int kb = ks * 32;
            unsigned ah[4], al[4], bh[4][2], bl[4][2];
            {
                const unsigned off = (unsigned)(kb + laneK) ^ aSw;
                ldsm4(ah, aBase + bufo + off);
                ldsm4(al, aBase + bufo + 16384u + off);
            }
#pragma unroll
            for (int p = 0; p < 2; p++) {
                const unsigned off = (unsigned)(kb + bKoff) ^ bSw[p];
                unsigned t[4];
                ldsm4(t, bBase[p] + off);
                bh[2 * p][0] = t[0]; bh[2 * p][1] = t[1];
                bh[2 * p + 1][0] = t[2]; bh[2 * p + 1][1] = t[3];
                ldsm4(t, bBase[p] + 32768u + off);
                bl[2 * p][0] = t[0]; bl[2 * p][1] = t[1];
                bl[2 * p + 1][0] = t[2]; bl[2 * p + 1][1] = t[3];
            }
#pragma unroll
            for (int nj = 0; nj < 4; nj++) {
                mma_bf16(c[nj], ah[0], ah[1], ah[2], ah[3], bh[nj][0], bh[nj][1]);
                mma_bf16(c[nj], ah[0], ah[1], ah[2], ah[3], bl[nj][0], bl[nj][1]);
                mma_bf16(c[nj], al[0], al[1], al[2], al[3], bh[nj][0], bh[nj][1]);
            }
        }

        float* obase = out + (size_t)chunk * 8192;
#pragma unroll
        for (int nj = 0; nj < 4; nj++) {
            const int col = n0 + nj * 8 + qc * 2;
            *(float2*)(obase + (m0 + qr) * 128 + col) =
                make_float2(c[nj][0], c[nj][1]);
            *(float2*)(obase + (m0 + 8 + qr) * 128 + col) =
                make_float2(c[nj][2], c[nj][3]);
        }
        __syncthreads();   // next tiles complete; everyone done with tiles[cur]
    }
}

// ============================================================================
extern "C" void kernel_launch(void* const* d_in, const int* in_sizes, int n_in,
                              void* d_out, int out_size)
{
    (void)in_sizes; (void)n_in; (void)out_size;
    const float* X     = (const float*)d_in[0];
    const float* Wq    = (const float*)d_in[1];
    const float* Wk    = (const float*)d_in[2];
    const float* Wv    = (const float*)d_in[3];
    const float* gamma = (const float*)d_in[4];
    const float* beta  = (const float*)d_in[5];
    float* out = (float*)d_out;

    cudaFuncSetAttribute(k1_kv_mma, cudaFuncAttributeMaxDynamicSharedMemorySize,
                         K1_SMEM);    // 226 KB
    cudaFuncSetAttribute(k3_out_mma, cudaFuncAttributeMaxDynamicSharedMemorySize,
                         K3_SMEM);    // 192 KB

    k1_kv_mma<<<NPART, 512, K1_SMEM>>>(X, Wk, Wv, gamma, beta);
    k2a_reduce<<<64, 256>>>();
    k2b_fold<<<256, 256>>>(Wq);
    k3_out_mma<<<NPART, 512, K3_SMEM>>>(X, out);
}

// round 10
// speedup vs baseline: 1.0224x; 1.0224x over previous
#include <cuda_runtime.h>
#include <cuda_bf16.h>

// Problem constants
#define NPART    148     // persistent CTAs (one per SM)
#define NCHUNK1  4096    // K1: chunks of 64 points  (262144/64);  b = chunk>>10
#define NCHUNK3  2048    // K3: chunks of 128 points (262144/128); b = chunk>>9

// Deterministic scratch (no cudaMalloc allowed)
__device__ float g_part[4 * NPART * 4096];   // per-CTA partial kv  [b][cta][h*1024+d*32+e]
__device__ float g_kv[4 * 4096];             // reduced kv          [b][h*1024+d*32+e]
__device__ float g_wqeff[4 * 16384];         // folded weights      [b][n*128 + c]  (n = e*4+h)

// ---- packed f32x2 helpers ----
__device__ __forceinline__ unsigned long long dup2(float x) {
    unsigned long long r;
    asm("mov.b64 %0, {%1, %1};" : "=l"(r) : "f"(x));
    return r;
}
__device__ __forceinline__ unsigned long long fma2(unsigned long long a,
                                                   unsigned long long b,
                                                   unsigned long long c) {
    unsigned long long d;
    asm("fma.rn.f32x2 %0, %1, %2, %3;" : "=l"(d) : "l"(a), "l"(b), "l"(c));
    return d;
}
__device__ __forceinline__ float2 unpk(unsigned long long a) {
    float2 f;
    asm("mov.b64 {%0, %1}, %2;" : "=f"(f.x), "=f"(f.y) : "l"(a));
    return f;
}

// ---- cp.async helpers ----
__device__ __forceinline__ void cp16(void* smem_dst, const float* gsrc) {
    unsigned s = (unsigned)__cvta_generic_to_shared(smem_dst);
    asm volatile("cp.async.cg.shared.global [%0], [%1], 16;" :: "r"(s), "l"(gsrc));
}
__device__ __forceinline__ void cp_commit() {
    asm volatile("cp.async.commit_group;");
}
__device__ __forceinline__ void cp_wait_all() {
    asm volatile("cp.async.wait_group 0;");
}

// ---- shared mma.sync infrastructure ----
// bf16 tile [rows][256 bytes], XOR-swizzled at 16B granularity.
__device__ __forceinline__ unsigned sw_off(int row, int kbyte) {
    return (unsigned)((row << 8) + (kbyte ^ ((row & 7) << 4)));
}
// fp32 staging [rows][1024 bytes], XOR-swizzled at 16B granularity.
__device__ __forceinline__ unsigned skv_off(int row, int colb) {
    return (unsigned)((row << 10) + (colb ^ ((row & 7) << 4)));
}

__device__ __forceinline__ void mma_bf16(float* c,
                                         unsigned a0, unsigned a1, unsigned a2, unsigned a3,
                                         unsigned b0, unsigned b1) {
    asm volatile(
        "mma.sync.aligned.m16n8k16.row.col.f32.bf16.bf16.f32 "
        "{%0,%1,%2,%3}, {%4,%5,%6,%7}, {%8,%9}, {%0,%1,%2,%3};"
        : "+f"(c[0]), "+f"(c[1]), "+f"(c[2]), "+f"(c[3])
        : "r"(a0), "r"(a1), "r"(a2), "r"(a3), "r"(b0), "r"(b1));
}

__device__ __forceinline__ void ldsm4(unsigned* r, unsigned a) {
    asm volatile("ldmatrix.sync.aligned.m8n8.x4.shared.b16 {%0,%1,%2,%3}, [%4];"
                 : "=r"(r[0]), "=r"(r[1]), "=r"(r[2]), "=r"(r[3]) : "r"(a));
}

// ============================================================================
// Kernel 1 (warp-specialized): 8 MMA warps (projection bf16x3 + LN) overlap
// 8 aux warps (outer product of previous chunk + X staging). 64-pt chunks.
// smem: WT 128K | XT 32K | sKV 64K | partk 1K | partv 1K | gb 1K = 227 KB
// ============================================================================
#define K1_WT_HI  0
#define K1_WT_LO  65536
#define K1_XT     131072     // hi at +0 (16K), lo at +16384 (16K)
#define K1_KV     163840     // 64 KB
#define K1_PARTK  229376
#define K1_PARTV  230400
#define K1_GB     231424
#define K1_SMEM   232448

__global__ void __launch_bounds__(512, 1)
k1_kv_mma(const float* __restrict__ X,
          const float* __restrict__ Wk, const float* __restrict__ Wv,
          const float* __restrict__ gamma, const float* __restrict__ beta)
{
    extern __shared__ char smem[];
    char* wth = smem + K1_WT_HI;
    char* wtl = smem + K1_WT_LO;
    char* xt  = smem + K1_XT;
    char* skv = smem + K1_KV;
    float2* partk = (float2*)(smem + K1_PARTK);
    float2* partv = (float2*)(smem + K1_PARTV);
    float2* gb    = (float2*)(smem + K1_GB);

    const unsigned xt_u  = (unsigned)__cvta_generic_to_shared(xt);
    const unsigned wth_u = (unsigned)__cvta_generic_to_shared(wth);

    const int tid  = threadIdx.x;
    const int lane = tid & 31;
    const int warp = tid >> 5;   // 16 warps: 0-7 MMA, 8-15 aux
    const int qr = lane >> 2;
    const int qc = lane & 3;

    // ---- One-time: transpose + bf16-split Wk|Wv into WT tiles (256 rows) ----
    for (int idx = tid; idx < 4096; idx += 512) {
        const int c  = idx >> 5;
        const int n4 = (idx & 31) << 2;
        const float4 wk = ((const float4*)Wk)[idx];
        const float4 wv = ((const float4*)Wv)[idx];
#pragma unroll
        for (int j = 0; j < 4; j++) {
            const float vk = (&wk.x)[j];
            const float vv = (&wv.x)[j];
            __nv_bfloat16 hk = __float2bfloat16(vk);
            __nv_bfloat16 hv = __float2bfloat16(vv);
            __nv_bfloat16 lk = __float2bfloat16(vk - __bfloat162float(hk));
            __nv_bfloat16 lv = __float2bfloat16(vv - __bfloat162float(hv));
            const unsigned ok = sw_off(n4 + j,       c * 2);
            const unsigned ov = sw_off(128 + n4 + j, c * 2);
            *(__nv_bfloat16*)(wth + ok) = hk;
            *(__nv_bfloat16*)(wtl + ok) = lk;
            *(__nv_bfloat16*)(wth + ov) = hv;
            *(__nv_bfloat16*)(wtl + ov) = lv;
        }
    }
    if (tid < 128) gb[tid] = make_float2(gamma[tid], beta[tid]);

    // ---------------- MMA-warp setup (warps 0-7) ----------------
    // warp tile: 32 rows x 64 cols over the 64 x 256 (k|v) output
    const int m0  = (warp & 1) * 32;
    const int n0g = ((warp & 7) >> 1) * 64;      // 0,64,128,192
    const int cg  = (warp & 7) >> 1;             // col group 0..3
    const int kw  = (cg < 2);                    // cols are k (else v)

    const int laneK = lane & 16;
    const int bKoff = (lane & 8) << 1;
    unsigned aBase[2], aSw[2], bBase[4], bSw[4];
#pragma unroll
    for (int mi = 0; mi < 2; mi++) {
        const int row = m0 + mi * 16 + (lane & 15);
        aSw[mi] = (unsigned)((row & 7) << 4);
        aBase[mi] = xt_u + row * 256;
    }
#pragma unroll
    for (int p = 0; p < 4; p++) {
        const int row = n0g + p * 16 + ((lane >> 1) & 8) + (lane & 7);
        bSw[p] = (unsigned)((row & 7) << 4);
        bBase[p] = wth_u + row * 256;
    }

    // ---------------- aux-warp setup (warps 8-15) ----------------
    const int aux = tid - 256;                   // 0..255 for aux warps
    const int hh   = (aux >> 6) & 3;
    const int idx2 = aux & 63;
    const int d0 = (idx2 >> 3) << 2;             // 0,4,...,28
    const int e0 = (idx2 & 7) << 2;              // 0,4,...,28
    const unsigned kcb = (unsigned)((hh * 32 + d0) * 4);
    const unsigned vcb = (unsigned)((128 + hh * 32 + e0) * 4);

    unsigned long long acc[4][2];
#pragma unroll
    for (int i = 0; i < 4; i++) { acc[i][0] = 0ull; acc[i][1] = 0ull; }

    // aux prolog: stage X(chunk0) into XT; keep X(chunk1) in regs
    float4 xr[8];
    const int chunk0 = blockIdx.x;
    if (warp >= 8) {
        const float4* src = (const float4*)X + (size_t)chunk0 * 2048;
#pragma unroll
        for (int i = 0; i < 8; i++) xr[i] = src[aux + i * 256];
#pragma unroll
        for (int i = 0; i < 8; i++) {
            const int idx = aux + i * 256;
            const int row = idx >> 5;
            const int kb  = (idx & 31) << 3;
            const float4 x = xr[i];
            __nv_bfloat162 h0 = __floats2bfloat162_rn(x.x, x.y);
            __nv_bfloat162 h1 = __floats2bfloat162_rn(x.z, x.w);
            float2 f0 = __bfloat1622float2(h0);
            float2 f1 = __bfloat1622float2(h1);
            __nv_bfloat162 l0 = __floats2bfloat162_rn(x.x - f0.x, x.y - f0.y);
            __nv_bfloat162 l1 = __floats2bfloat162_rn(x.z - f1.x, x.w - f1.y);
            const unsigned off = sw_off(row, kb);
            *(__nv_bfloat162*)(xt + off)             = h0;
            *(__nv_bfloat162*)(xt + off + 4)         = h1;
            *(__nv_bfloat162*)(xt + 16384 + off)     = l0;
            *(__nv_bfloat162*)(xt + 16384 + off + 4) = l1;
        }
        const int c1 = chunk0 + NPART;
        if (c1 < NCHUNK1) {
            const float4* s1 = (const float4*)X + (size_t)c1 * 2048;
#pragma unroll
            for (int i = 0; i < 8; i++) xr[i] = s1[aux + i * 256];
        }
    }
    __syncthreads();

    int pend = -1, ob = -1;
    float c[2][8][4];

    for (int chunk = chunk0; chunk < NCHUNK1; chunk += NPART) {
        // ================= PHASE A =================
        if (warp < 8) {
            // projection MMA (bf16x3) on XT
#pragma unroll
            for (int mi = 0; mi < 2; mi++)
#pragma unroll
                for (int nj = 0; nj < 8; nj++)
#pragma unroll
                    for (int z = 0; z < 4; z++) c[mi][nj][z] = 0.f;

#pragma unroll
            for (int ks = 0; ks < 8; ks++) {
                const int kb = ks * 32;
                unsigned ah[2][4], al[2][4];
#pragma unroll
                for (int mi = 0; mi < 2; mi++) {
                    const unsigned off = (unsigned)(kb + laneK) ^ aSw[mi];
                    ldsm4(ah[mi], aBase[mi] + off);
                    ldsm4(al[mi], aBase[mi] + 16384u + off);
                }
#pragma unroll
                for (int p = 0; p < 4; p++) {
                    const unsigned off = (unsigned)(kb + bKoff) ^ bSw[p];
                    unsigned th[4], tl[4];
                    ldsm4(th, bBase[p] + off);
                    ldsm4(tl, bBase[p] + 65536u + off);
#pragma unroll
                    for (int mi = 0; mi < 2; mi++) {
                        float* c0 = c[mi][2 * p];
                        float* c1 = c[mi][2 * p + 1];
                        mma_bf16(c0, ah[mi][0], ah[mi][1], ah[mi][2], ah[mi][3], th[0], th[1]);
                        mma_bf16(c0, ah[mi][0], ah[mi][1], ah[mi][2], ah[mi][3], tl[0], tl[1]);
                        mma_bf16(c0, al[mi][0], al[mi][1], al[mi][2], al[mi][3], th[0], th[1]);
                        mma_bf16(c1, ah[mi][0], ah[mi][1], ah[mi][2], ah[mi][3], th[2], th[3]);
                        mma_bf16(c1, ah[mi][0], ah[mi][1], ah[mi][2], ah[mi][3], tl[2], tl[3]);
                        mma_bf16(c1, al[mi][0], al[mi][1], al[mi][2], al[mi][3], th[2], th[3]);
                    }
                }
            }

            // LN partial stats over this warp's 64 cols
#pragma unroll
            for (int mi = 0; mi < 2; mi++) {
#pragma unroll
                for (int half = 0; half < 2; half++) {
                    float s = 0.f, q = 0.f;
#pragma unroll
                    for (int nj = 0; nj < 8; nj++) {
                        const float v0 = c[mi][nj][half * 2];
                        const float v1 = c[mi][nj][half * 2 + 1];
                        s += v0 + v1;
                        q += v0 * v0 + v1 * v1;
                    }
                    s += __shfl_xor_sync(0xffffffffu, s, 1);
                    q += __shfl_xor_sync(0xffffffffu, q, 1);
                    s += __shfl_xor_sync(0xffffffffu, s, 2);
                    q += __shfl_xor_sync(0xffffffffu, q, 2);
                    if (qc == 0) {
                        const int row = m0 + mi * 16 + half * 8 + qr;
                        (kw ? partk : partv)[row * 2 + (cg & 1)] = make_float2(s, q);
                    }
                }
            }
        } else {
            // outer product for PREVIOUS chunk (overlaps MMA warps)
            if (pend >= 0) {
                const int bj = pend >> 10;
                if (bj != ob) {
                    if (ob >= 0) {
                        float* dst = g_part + ((size_t)ob * NPART + blockIdx.x) * 4096
                                   + hh * 1024 + d0 * 32 + e0;
#pragma unroll
                        for (int i = 0; i < 4; i++) {
                            float2 lo = unpk(acc[i][0]);
                            float2 hi = unpk(acc[i][1]);
                            *(float4*)(dst + i * 32) = make_float4(lo.x, lo.y, hi.x, hi.y);
                            acc[i][0] = 0ull; acc[i][1] = 0ull;
                        }
                    }
                    ob = bj;
                }
#pragma unroll 8
                for (int p = 0; p < 64; p++) {
                    const float4 kk = *(const float4*)(skv + skv_off(p, kcb));
                    const ulonglong2 vv = *(const ulonglong2*)(skv + skv_off(p, vcb));
                    unsigned long long k0 = dup2(kk.x), k1 = dup2(kk.y);
                    unsigned long long k2 = dup2(kk.z), k3 = dup2(kk.w);
                    acc[0][0] = fma2(vv.x, k0, acc[0][0]); acc[0][1] = fma2(vv.y, k0, acc[0][1]);
                    acc[1][0] = fma2(vv.x, k1, acc[1][0]); acc[1][1] = fma2(vv.y, k1, acc[1][1]);
                    acc[2][0] = fma2(vv.x, k2, acc[2][0]); acc[2][1] = fma2(vv.y, k2, acc[2][1]);
                    acc[3][0] = fma2(vv.x, k3, acc[3][0]); acc[3][1] = fma2(vv.y, k3, acc[3][1]);
                }
            }
        }
        __syncthreads();   // bar1: partials + sKV reads done

        // ================= PHASE B =================
        if (warp < 8) {
            // stats + normalize + store kn/vn (fp32, swizzled) to sKV
            const float2* pk = kw ? partk : partv;
#pragma unroll
            for (int mi = 0; mi < 2; mi++) {
#pragma unroll
                for (int half = 0; half < 2; half++) {
                    const int row = m0 + mi * 16 + half * 8 + qr;
                    const float2 p0 = pk[row * 2];
                    const float2 p1 = pk[row * 2 + 1];
                    const float mu = (p0.x + p1.x) * (1.f / 128.f);
                    const float ms = (p0.y + p1.y) * (1.f / 128.f);
                    const float rr = rsqrtf(ms - mu * mu + 1e-5f);
                    const float mm = -mu * rr;
#pragma unroll
                    for (int nj = 0; nj < 8; nj++) {
                        const int ch = (n0g + nj * 8 + qc * 2) & 127;
                        const float2 g0 = gb[ch];
                        const float2 g1 = gb[ch + 1];
                        float& v0 = c[mi][nj][half * 2];
                        float& v1 = c[mi][nj][half * 2 + 1];
                        v0 = fmaf(fmaf(v0, rr, mm), g0.x, g0.y);
                        v1 = fmaf(fmaf(v1, rr, mm), g1.x, g1.y);
                    }
                }
            }
#pragma unroll
            for (int mi = 0; mi < 2; mi++) {
                const int r = m0 + mi * 16 + qr;
#pragma unroll
                for (int nj = 0; nj < 8; nj++) {
                    const int colb = (n0g + nj * 8 + qc * 2) * 4;
                    *(float2*)(skv + skv_off(r,     colb)) = make_float2(c[mi][nj][0], c[mi][nj][1]);
                    *(float2*)(skv + skv_off(r + 8, colb)) = make_float2(c[mi][nj][2], c[mi][nj][3]);
                }
            }
        } else {
            // cvt X(i+1) regs -> XT, then prefetch X(i+2) regs
            const int nxt = chunk + NPART;
            if (nxt < NCHUNK1) {
#pragma unroll
                for (int i = 0; i < 8; i++) {
                    const int idx = aux + i * 256;
                    const int row = idx >> 5;
                    const int kb  = (idx & 31) << 3;
                    const float4 x = xr[i];
                    __nv_bfloat162 h0 = __floats2bfloat162_rn(x.x, x.y);
                    __nv_bfloat162 h1 = __floats2bfloat162_rn(x.z, x.w);
                    float2 f0 = __bfloat1622float2(h0);
                    float2 f1 = __bfloat1622float2(h1);
                    __nv_bfloat162 l0 = __floats2bfloat162_rn(x.x - f0.x, x.y - f0.y);
                    __nv_bfloat162 l1 = __floats2bfloat162_rn(x.z - f1.x, x.w - f1.y);
                    const unsigned off = sw_off(row, kb);
                    *(__nv_bfloat162*)(xt + off)             = h0;
                    *(__nv_bfloat162*)(xt + off + 4)         = h1;
                    *(__nv_bfloat162*)(xt + 16384 + off)     = l0;
                    *(__nv_bfloat162*)(xt + 16384 + off + 4) = l1;
                }
                const int nxt2 = nxt + NPART;
                if (nxt2 < NCHUNK1) {
                    const float4* src = (const float4*)X + (size_t)nxt2 * 2048;
#pragma unroll
                    for (int i = 0; i < 8; i++) xr[i] = src[aux + i * 256];
                }
            }
        }
        pend = chunk;
        __syncthreads();   // bar2: sKV(i) + XT(i+1) complete
    }

    // Epilogue: aux warps run the outer product for the final chunk + flush
    if (warp >= 8 && pend >= 0) {
        const int bj = pend >> 10;
        if (bj != ob) {
            if (ob >= 0) {
                float* dst = g_part + ((size_t)ob * NPART + blockIdx.x) * 4096
                           + hh * 1024 + d0 * 32 + e0;
#pragma unroll
                for (int i = 0; i < 4; i++) {
                    float2 lo = unpk(acc[i][0]);
                    float2 hi = unpk(acc[i][1]);
                    *(float4*)(dst + i * 32) = make_float4(lo.x, lo.y, hi.x, hi.y);
                    acc[i][0] = 0ull; acc[i][1] = 0ull;
                }
            }
            ob = bj;
        }
#pragma unroll 8
        for (int p = 0; p < 64; p++) {
            const float4 kk = *(const float4*)(skv + skv_off(p, kcb));
            const ulonglong2 vv = *(const ulonglong2*)(skv + skv_off(p, vcb));
            unsigned long long k0 = dup2(kk.x), k1 = dup2(kk.y);
            unsigned long long k2 = dup2(kk.z), k3 = dup2(kk.w);
            acc[0][0] = fma2(vv.x, k0, acc[0][0]); acc[0][1] = fma2(vv.y, k0, acc[0][1]);
            acc[1][0] = fma2(vv.x, k1, acc[1][0]); acc[1][1] = fma2(vv.y, k1, acc[1][1]);
            acc[2][0] = fma2(vv.x, k2, acc[2][0]); acc[2][1] = fma2(vv.y, k2, acc[2][1]);
            acc[3][0] = fma2(vv.x, k3, acc[3][0]); acc[3][1] = fma2(vv.y, k3, acc[3][1]);
        }
        float* dst = g_part + ((size_t)ob * NPART + blockIdx.x) * 4096
                   + hh * 1024 + d0 * 32 + e0;
#pragma unroll
        for (int i = 0; i < 4; i++) {
            float2 lo = unpk(acc[i][0]);
            float2 hi = unpk(acc[i][1]);
            *(float4*)(dst + i * 32) = make_float4(lo.x, lo.y, hi.x, hi.y);
        }
    }
}

// ============================================================================
// Kernel 2a: reduce 148 per-CTA partials -> g_kv.
// ============================================================================
__global__ void k2a_reduce()
{
    const int gid = blockIdx.x * 256 + threadIdx.x;
    const int b = gid >> 12;
    const int e = gid & 4095;
    const float* src = g_part + (size_t)b * NPART * 4096 + e;
    float s = 0.f;
#pragma unroll 4
    for (int j = 0; j < NPART; j++) s += src[(size_t)j * 4096];
    g_kv[gid] = s;
}

// ============================================================================
// Kernel 2b: Wq_eff[b][n][c] = (1/N) * sum_d Wq[c][h*32+d] * kv[b][h][d][e]
// ============================================================================
__global__ void k2b_fold(const float* __restrict__ Wq)
{
    const int gid = blockIdx.x * 256 + threadIdx.x;
    const int b  = gid >> 14;
    const int r  = gid & 16383;
    const int cp = r >> 7;
    const int co = r & 127;
    const int e  = co >> 2;
    const int h  = co & 3;
    const float* wq = Wq + cp * 128 + h * 32;
    const float* kv = g_kv + b * 4096 + h * 1024 + e;
    float s = 0.f;
#pragma unroll
    for (int d = 0; d < 32; d++) s += wq[d] * kv[d * 32];
    g_wqeff[b * 16384 + co * 128 + cp] = s * (1.f / 65536.f);
}

// ============================================================================
// Kernel 3 (round-8 version, best known): out = X @ Wq_eff[b]^T (bf16x3)
// 128-pt chunks, cp.async raw staging, ldmatrix fragments.
// smem: Whi 32K | Wlo 32K | Xhi 32K | Xlo 32K | raw 64K = 192 KB
// ============================================================================
#define K3S_W_HI 0
#define K3S_W_LO 32768
#define K3S_X_HI 65536
#define K3S_X_LO 98304
#define K3S_RAW  131072
#define K3_SMEM  196608

__device__ __forceinline__ void cvt_tile512(const float* __restrict__ src,
                                            char* hi_base, char* lo_base, int tid) {
#pragma unroll
    for (int i = 0; i < 8; i++) {
        const int idx = tid + i * 512;
        const int row = idx >> 5;
        const int kb  = (idx & 31) << 3;
        const float4 x = *(const float4*)(src + idx * 4);
        __nv_bfloat162 h0 = __floats2bfloat162_rn(x.x, x.y);
        __nv_bfloat162 h1 = __floats2bfloat162_rn(x.z, x.w);
        float2 f0 = __bfloat1622float2(h0);
        float2 f1 = __bfloat1622float2(h1);
        __nv_bfloat162 l0 = __floats2bfloat162_rn(x.x - f0.x, x.y - f0.y);
        __nv_bfloat162 l1 = __floats2bfloat162_rn(x.z - f1.x, x.w - f1.y);
        const unsigned off = sw_off(row, kb);
        *(__nv_bfloat162*)(hi_base + off)     = h0;
        *(__nv_bfloat162*)(hi_base + off + 4) = h1;
        *(__nv_bfloat162*)(lo_base + off)     = l0;
        *(__nv_bfloat162*)(lo_base + off + 4) = l1;
    }
}

__device__ __forceinline__ void cvt_w512(const float* __restrict__ src,
                                         char* hi_base, char* lo_base, int tid) {
    if (tid < 256) {
#pragma unroll
        for (int i = 0; i < 16; i++) {
            const int idx = tid + i * 256;
            const int row = idx >> 5;
            const int kb  = (idx & 31) << 3;
            const float4 x = *(const float4*)(src + idx * 4);
            __nv_bfloat162 h0 = __floats2bfloat162_rn(x.x, x.y);
            __nv_bfloat162 h1 = __floats2bfloat162_rn(x.z, x.w);
            float2 f0 = __bfloat1622float2(h0);
            float2 f1 = __bfloat1622float2(h1);
            __nv_bfloat162 l0 = __floats2bfloat162_rn(x.x - f0.x, x.y - f0.y);
            __nv_bfloat162 l1 = __floats2bfloat162_rn(x.z - f1.x, x.w - f1.y);
            const unsigned off = sw_off(row, kb);
            *(__nv_bfloat162*)(hi_base + off)     = h0;
            *(__nv_bfloat162*)(hi_base + off + 4) = h1;
            *(__nv_bfloat162*)(lo_base + off)     = l0;
            *(__nv_bfloat162*)(lo_base + off + 4) = l1;
        }
    }
}

__global__ void __launch_bounds__(512, 1)
k3_out_mma(const float* __restrict__ X, float* __restrict__ out)
{
    extern __shared__ char smem[];
    const int tid  = threadIdx.x;
    const int lane = tid & 31;
    const int warp = tid >> 5;   // 16 warps

    const int m0 = (warp & 3) * 32;
    const int n0 = (warp >> 2) * 32;
    const int qr = lane >> 2;
    const int qc = lane & 3;

    float* raw = (float*)(smem + K3S_RAW);

    const unsigned xh_u = (unsigned)__cvta_generic_to_shared(smem + K3S_X_HI);
    const unsigned wh_u = (unsigned)__cvta_generic_to_shared(smem + K3S_W_HI);

    const int laneK = lane & 16;
    const int bKoff = (lane & 8) << 1;
    unsigned aBase[2], aSw[2], bBase[2], bSw[2];
#pragma unroll
    for (int mi = 0; mi < 2; mi++) {
        const int row = m0 + mi * 16 + (lane & 15);
        aSw[mi] = (unsigned)((row & 7) << 4);
        aBase[mi] = xh_u + row * 256;
    }
#pragma unroll
    for (int p = 0; p < 2; p++) {
        const int row = n0 + p * 16 + ((lane >> 1) & 8) + (lane & 7);
        bSw[p] = (unsigned)((row & 7) << 4);
        bBase[p] = wh_u + row * 256;
    }

    // Prologue: cp.async first chunk's raw X
    {
        const float* src = X + (size_t)blockIdx.x * 16384;
#pragma unroll
        for (int i = 0; i < 8; i++)
            cp16(raw + (tid + i * 512) * 4, src + (tid + i * 512) * 4);
        cp_commit();
    }

    int cur_b = -1;
    for (int chunk = blockIdx.x; chunk < NCHUNK3; chunk += NPART) {
        const int b = chunk >> 9;

        cp_wait_all();
        __syncthreads();   // raw ready; all prev MMA tile reads done

        if (b != cur_b) {
            cvt_w512(g_wqeff + b * 16384, smem + K3S_W_HI, smem + K3S_W_LO, tid);
            cur_b = b;
        }
        cvt_tile512(raw, smem + K3S_X_HI, smem + K3S_X_LO, tid);
        __syncthreads();   // tiles visible; all raw reads done

        // prefetch next chunk
        {
            const int nxt = chunk + NPART;
            if (nxt < NCHUNK3) {
                const float* src = X + (size_t)nxt * 16384;
#pragma unroll
                for (int i = 0; i < 8; i++)
                    cp16(raw + (tid + i * 512) * 4, src + (tid + i * 512) * 4);
                cp_commit();
            }
        }

        float c[2][4][4];
#pragma unroll
        for (int mi = 0; mi < 2; mi++)
#pragma unroll
            for (int nj = 0; nj < 4; nj++)
#pragma unroll
                for (int z = 0; z < 4; z++) c[mi][nj][z] = 0.f;

#pragma unroll
        for (int ks = 0; ks < 8; ks++) {
            const int kb = ks * 32;
            unsigned ah[2][4], al[2][4], bh[4][2], bl[4][2];
#pragma unroll
            for (int mi = 0; mi < 2; mi++) {
                const unsigned off = (unsigned)(kb + laneK) ^ aSw[mi];
                ldsm4(ah[mi], aBase[mi] + off);
                ldsm4(al[mi], aBase[mi] + 32768u + off);
            }
#pragma unroll
            for (int p = 0; p < 2; p++) {
                const unsigned off = (unsigned)(kb + bKoff) ^ bSw[p];
                unsigned t[4];
                ldsm4(t, bBase[p] + off);
                bh[2 * p][0] = t[0]; bh[2 * p][1] = t[1];
                bh[2 * p + 1][0] = t[2]; bh[2 * p + 1][1] = t[3];
                ldsm4(t, bBase[p] + 32768u + off);
                bl[2 * p][0] = t[0]; bl[2 * p][1] = t[1];
                bl[2 * p + 1][0] = t[2]; bl[2 * p + 1][1] = t[3];
            }
#pragma unroll
            for (int mi = 0; mi < 2; mi++)
#pragma unroll
                for (int nj = 0; nj < 4; nj++) {
                    mma_bf16(c[mi][nj], ah[mi][0], ah[mi][1], ah[mi][2], ah[mi][3],
                             bh[nj][0], bh[nj][1]);
                    mma_bf16(c[mi][nj], ah[mi][0], ah[mi][1], ah[mi][2], ah[mi][3],
                             bl[nj][0], bl[nj][1]);
                    mma_bf16(c[mi][nj], al[mi][0], al[mi][1], al[mi][2], al[mi][3],
                             bh[nj][0], bh[nj][1]);
                }
        }

        float* obase = out + (size_t)chunk * 16384;
#pragma unroll
        for (int mi = 0; mi < 2; mi++) {
            const int r = m0 + mi * 16 + qr;
#pragma unroll
            for (int nj = 0; nj < 4; nj++) {
                const int col = n0 + nj * 8 + qc * 2;
                *(float2*)(obase + r * 128 + col) =
                    make_float2(c[mi][nj][0], c[mi][nj][1]);
                *(float2*)(obase + (r + 8) * 128 + col) =
                    make_float2(c[mi][nj][2], c[mi][nj][3]);
            }
        }
    }
}

// ============================================================================
extern "C" void kernel_launch(void* const* d_in, const int* in_sizes, int n_in,
                              void* d_out, int out_size)
{
    (void)in_sizes; (void)n_in; (void)out_size;
    const float* X     = (const float*)d_in[0];
    const float* Wq    = (const float*)d_in[1];
    const float* Wk    = (const float*)d_in[2];
    const float* Wv    = (const float*)d_in[3];
    const float* gamma = (const float*)d_in[4];
    const float* beta  = (const float*)d_in[5];
    float* out = (float*)d_out;

    cudaFuncSetAttribute(k1_kv_mma, cudaFuncAttributeMaxDynamicSharedMemorySize,
                         K1_SMEM);    // 227 KB
    cudaFuncSetAttribute(k3_out_mma, cudaFuncAttributeMaxDynamicSharedMemorySize,
                         K3_SMEM);    // 192 KB

    k1_kv_mma<<<NPART, 512, K1_SMEM>>>(X, Wk, Wv, gamma, beta);
    k2a_reduce<<<64, 256>>>();
    k2b_fold<<<256, 256>>>(Wq);
    k3_out_mma<<<NPART, 512, K3_SMEM>>>(X, out);
}

// round 11
// speedup vs baseline: 1.0848x; 1.0611x over previous
#include <cuda_runtime.h>
#include <cuda_bf16.h>

// Problem constants
#define NPART    148     // persistent CTAs (one per SM)
#define NCHUNK1  4096    // K1: chunks of 64 points  (262144/64);  b = chunk>>10
#define NCHUNK3  2048    // K3: chunks of 128 points (262144/128); b = chunk>>9

// Deterministic scratch (no cudaMalloc allowed)
__device__ float g_part[4 * NPART * 4096];   // per-CTA partial kv  [b][cta][h*1024+d*32+e]
__device__ float g_kv[4 * 4096];             // reduced kv          [b][h*1024+d*32+e]
__device__ float g_wqeff[4 * 16384];         // folded weights      [b][n*128 + c]  (n = e*4+h)

// ---- cp.async helpers ----
__device__ __forceinline__ void cp16(void* smem_dst, const float* gsrc) {
    unsigned s = (unsigned)__cvta_generic_to_shared(smem_dst);
    asm volatile("cp.async.cg.shared.global [%0], [%1], 16;" :: "r"(s), "l"(gsrc));
}
__device__ __forceinline__ void cp_commit() {
    asm volatile("cp.async.commit_group;");
}
__device__ __forceinline__ void cp_wait_all() {
    asm volatile("cp.async.wait_group 0;");
}

// ---- shared mma.sync infrastructure ----
// bf16 tile [rows][256 bytes], XOR-swizzled at 16B granularity.
__device__ __forceinline__ unsigned sw_off(int row, int kbyte) {
    return (unsigned)((row << 8) + (kbyte ^ ((row & 7) << 4)));
}
// bf16 kn/vn tile [64 rows][512 bytes], XOR-swizzled at 16B granularity.
__device__ __forceinline__ unsigned skvb_off(int row, int chb) {
    return (unsigned)((row << 9) + (chb ^ ((row & 7) << 4)));
}

__device__ __forceinline__ void mma_bf16(float* c,
                                         unsigned a0, unsigned a1, unsigned a2, unsigned a3,
                                         unsigned b0, unsigned b1) {
    asm volatile(
        "mma.sync.aligned.m16n8k16.row.col.f32.bf16.bf16.f32 "
        "{%0,%1,%2,%3}, {%4,%5,%6,%7}, {%8,%9}, {%0,%1,%2,%3};"
        : "+f"(c[0]), "+f"(c[1]), "+f"(c[2]), "+f"(c[3])
        : "r"(a0), "r"(a1), "r"(a2), "r"(a3), "r"(b0), "r"(b1));
}

__device__ __forceinline__ void ldsm4(unsigned* r, unsigned a) {
    asm volatile("ldmatrix.sync.aligned.m8n8.x4.shared.b16 {%0,%1,%2,%3}, [%4];"
                 : "=r"(r[0]), "=r"(r[1]), "=r"(r[2]), "=r"(r[3]) : "r"(a));
}
__device__ __forceinline__ void ldsm4t(unsigned* r, unsigned a) {
    asm volatile("ldmatrix.sync.aligned.m8n8.x4.trans.shared.b16 {%0,%1,%2,%3}, [%4];"
                 : "=r"(r[0]), "=r"(r[1]), "=r"(r[2]), "=r"(r[3]) : "r"(a));
}

// ============================================================================
// Kernel 1: 8 proj-MMA warps (X@(Wk|Wv) bf16x3 + LN) overlap 8 aux warps
// (tensor-core outer product kv += kn^T vn via ldmatrix.trans + X staging).
// kn/vn stored as bf16 hi/lo tiles; outer accumulators live in registers
// across each batch (g_part written only at batch boundaries).
// smem: WT 128K | XT 32K | KVH 32K | KVL 32K | partk/v 2K | gb 1K = 227 KB
// ============================================================================
#define K1_WT_HI  0
#define K1_WT_LO  65536
#define K1_XT     131072     // hi at +0 (16K), lo at +16384 (16K)
#define K1_KVH    163840     // [64 pt][256 ch] bf16 hi (32K)
#define K1_KVL    196608     // lo (32K)
#define K1_PARTK  229376
#define K1_PARTV  230400
#define K1_GB     231424
#define K1_SMEM   232448

__global__ void __launch_bounds__(512, 1)
k1_kv_mma(const float* __restrict__ X,
          const float* __restrict__ Wk, const float* __restrict__ Wv,
          const float* __restrict__ gamma, const float* __restrict__ beta)
{
    extern __shared__ char smem[];
    char* wth = smem + K1_WT_HI;
    char* wtl = smem + K1_WT_LO;
    char* xt  = smem + K1_XT;
    char* kvh = smem + K1_KVH;
    char* kvl = smem + K1_KVL;
    float2* partk = (float2*)(smem + K1_PARTK);
    float2* partv = (float2*)(smem + K1_PARTV);
    float2* gb    = (float2*)(smem + K1_GB);

    const unsigned xt_u  = (unsigned)__cvta_generic_to_shared(xt);
    const unsigned wth_u = (unsigned)__cvta_generic_to_shared(wth);
    const unsigned kvh_u = (unsigned)__cvta_generic_to_shared(kvh);

    const int tid  = threadIdx.x;
    const int lane = tid & 31;
    const int warp = tid >> 5;   // 16 warps: 0-7 proj MMA, 8-15 aux
    const int qr = lane >> 2;
    const int qc = lane & 3;

    // ---- One-time: transpose + bf16-split Wk|Wv into WT tiles (256 rows) ----
    for (int idx = tid; idx < 4096; idx += 512) {
        const int c  = idx >> 5;
        const int n4 = (idx & 31) << 2;
        const float4 wk = ((const float4*)Wk)[idx];
        const float4 wv = ((const float4*)Wv)[idx];
#pragma unroll
        for (int j = 0; j < 4; j++) {
            const float vk = (&wk.x)[j];
            const float vv = (&wv.x)[j];
            __nv_bfloat16 hk = __float2bfloat16(vk);
            __nv_bfloat16 hv = __float2bfloat16(vv);
            __nv_bfloat16 lk = __float2bfloat16(vk - __bfloat162float(hk));
            __nv_bfloat16 lv = __float2bfloat16(vv - __bfloat162float(hv));
            const unsigned ok = sw_off(n4 + j,       c * 2);
            const unsigned ov = sw_off(128 + n4 + j, c * 2);
            *(__nv_bfloat16*)(wth + ok) = hk;
            *(__nv_bfloat16*)(wtl + ok) = lk;
            *(__nv_bfloat16*)(wth + ov) = hv;
            *(__nv_bfloat16*)(wtl + ov) = lv;
        }
    }
    if (tid < 128) gb[tid] = make_float2(gamma[tid], beta[tid]);

    // ---------------- proj-MMA warp setup (warps 0-7) ----------------
    // warp tile: 32 rows x 64 cols over the 64 x 256 (k|v) output
    const int m0  = (warp & 1) * 32;
    const int n0g = ((warp & 7) >> 1) * 64;      // 0,64,128,192
    const int cg  = (warp & 7) >> 1;
    const int kw  = (cg < 2);

    const int laneK = lane & 16;
    const int bKoff = (lane & 8) << 1;
    unsigned aBase[2], aSw[2], bBase[4], bSw[4];
#pragma unroll
    for (int mi = 0; mi < 2; mi++) {
        const int row = m0 + mi * 16 + (lane & 15);
        aSw[mi] = (unsigned)((row & 7) << 4);
        aBase[mi] = xt_u + row * 256;
    }
#pragma unroll
    for (int p = 0; p < 4; p++) {
        const int row = n0g + p * 16 + ((lane >> 1) & 8) + (lane & 7);
        bSw[p] = (unsigned)((row & 7) << 4);
        bBase[p] = wth_u + row * 256;
    }

    // ---------------- aux warp setup (warps 8-15) ----------------
    // aux warp aw: head hh2 = aw>>1, half2 = aw&1 owns kv rows d = half2*16..+15,
    // cols e = 0..31 (4 m16n8 tiles). Contraction dim = points (4 ksteps of 16).
    const int aw    = warp - 8;
    const int hh2   = (aw >> 1) & 3;
    const int half2 = aw & 1;
    // A (k^T) trans-ldsm: stored [p][ch], ch = hh2*32 + d
    const int rkA = (lane & 7) + ((lane >> 4) & 1) * 8;
    const unsigned chbA = (unsigned)(hh2 * 64 + half2 * 32 + ((lane >> 3) & 1) * 16);
    const unsigned aOut = kvh_u + rkA * 512 + (chbA ^ ((unsigned)(rkA & 7) << 4));
    // B (v) trans-ldsm: stored [p][ch], ch = 128 + hh2*32 + e
    const int rkB = (lane & 7) + ((lane >> 3) & 1) * 8;
    const unsigned swB = (unsigned)(rkB & 7) << 4;
    const unsigned chbB = (unsigned)(256 + hh2 * 64 + ((lane >> 4) & 1) * 16);
    const unsigned bOut0 = kvh_u + rkB * 512 + (chbB ^ swB);          // e tiles 0,1
    const unsigned bOut1 = kvh_u + rkB * 512 + ((chbB + 32) ^ swB);   // e tiles 2,3

    float co[4][4];
#pragma unroll
    for (int nt = 0; nt < 4; nt++)
#pragma unroll
        for (int z = 0; z < 4; z++) co[nt][z] = 0.f;

    // aux prolog: stage X(chunk0) into XT; keep X(chunk1) in regs
    float4 xr[8];
    const int aux = tid - 256;
    const int chunk0 = blockIdx.x;
    if (warp >= 8) {
        const float4* src = (const float4*)X + (size_t)chunk0 * 2048;
#pragma unroll
        for (int i = 0; i < 8; i++) xr[i] = src[aux + i * 256];
#pragma unroll
        for (int i = 0; i < 8; i++) {
            const int idx = aux + i * 256;
            const int row = idx >> 5;
            const int kb  = (idx & 31) << 3;
            const float4 x = xr[i];
            __nv_bfloat162 h0 = __floats2bfloat162_rn(x.x, x.y);
            __nv_bfloat162 h1 = __floats2bfloat162_rn(x.z, x.w);
            float2 f0 = __bfloat1622float2(h0);
            float2 f1 = __bfloat1622float2(h1);
            __nv_bfloat162 l0 = __floats2bfloat162_rn(x.x - f0.x, x.y - f0.y);
            __nv_bfloat162 l1 = __floats2bfloat162_rn(x.z - f1.x, x.w - f1.y);
            const unsigned off = sw_off(row, kb);
            *(__nv_bfloat162*)(xt + off)             = h0;
            *(__nv_bfloat162*)(xt + off + 4)         = h1;
            *(__nv_bfloat162*)(xt + 16384 + off)     = l0;
            *(__nv_bfloat162*)(xt + 16384 + off + 4) = l1;
        }
        const int c1 = chunk0 + NPART;
        if (c1 < NCHUNK1) {
            const float4* s1 = (const float4*)X + (size_t)c1 * 2048;
#pragma unroll
            for (int i = 0; i < 8; i++) xr[i] = s1[aux + i * 256];
        }
    }
    __syncthreads();

    int pend = -1, ob = -1;
    float c[2][8][4];

    for (int chunk = chunk0; chunk < NCHUNK1; chunk += NPART) {
        // ================= PHASE A =================
        if (warp < 8) {
            // projection MMA (bf16x3) on XT
#pragma unroll
            for (int mi = 0; mi < 2; mi++)
#pragma unroll
                for (int nj = 0; nj < 8; nj++)
#pragma unroll
                    for (int z = 0; z < 4; z++) c[mi][nj][z] = 0.f;

#pragma unroll
            for (int ks = 0; ks < 8; ks++) {
                const int kb = ks * 32;
                unsigned ah[2][4], al[2][4];
#pragma unroll
                for (int mi = 0; mi < 2; mi++) {
                    const unsigned off = (unsigned)(kb + laneK) ^ aSw[mi];
                    ldsm4(ah[mi], aBase[mi] + off);
                    ldsm4(al[mi], aBase[mi] + 16384u + off);
                }
#pragma unroll
                for (int p = 0; p < 4; p++) {
                    const unsigned off = (unsigned)(kb + bKoff) ^ bSw[p];
                    unsigned th[4], tl[4];
                    ldsm4(th, bBase[p] + off);
                    ldsm4(tl, bBase[p] + 65536u + off);
#pragma unroll
                    for (int mi = 0; mi < 2; mi++) {
                        float* c0 = c[mi][2 * p];
                        float* c1 = c[mi][2 * p + 1];
                        mma_bf16(c0, ah[mi][0], ah[mi][1], ah[mi][2], ah[mi][3], th[0], th[1]);
                        mma_bf16(c0, ah[mi][0], ah[mi][1], ah[mi][2], ah[mi][3], tl[0], tl[1]);
                        mma_bf16(c0, al[mi][0], al[mi][1], al[mi][2], al[mi][3], th[0], th[1]);
                        mma_bf16(c1, ah[mi][0], ah[mi][1], ah[mi][2], ah[mi][3], th[2], th[3]);
                        mma_bf16(c1, ah[mi][0], ah[mi][1], ah[mi][2], ah[mi][3], tl[2], tl[3]);
                        mma_bf16(c1, al[mi][0], al[mi][1], al[mi][2], al[mi][3], th[2], th[3]);
                    }
                }
            }

            // LN partial stats over this warp's 64 cols
#pragma unroll
            for (int mi = 0; mi < 2; mi++) {
#pragma unroll
                for (int half = 0; half < 2; half++) {
                    float s = 0.f, q = 0.f;
#pragma unroll
                    for (int nj = 0; nj < 8; nj++) {
                        const float v0 = c[mi][nj][half * 2];
                        const float v1 = c[mi][nj][half * 2 + 1];
                        s += v0 + v1;
                        q += v0 * v0 + v1 * v1;
                    }
                    s += __shfl_xor_sync(0xffffffffu, s, 1);
                    q += __shfl_xor_sync(0xffffffffu, q, 1);
                    s += __shfl_xor_sync(0xffffffffu, s, 2);
                    q += __shfl_xor_sync(0xffffffffu, q, 2);
                    if (qc == 0) {
                        const int row = m0 + mi * 16 + half * 8 + qr;
                        (kw ? partk : partv)[row * 2 + (cg & 1)] = make_float2(s, q);
                    }
                }
            }
        } else {
            // tensor-core outer product for PREVIOUS chunk (kv += kn^T vn)
            if (pend >= 0) {
                const int bj = pend >> 10;
                if (bj != ob) {
                    if (ob >= 0) {
                        float* dst = g_part + ((size_t)ob * NPART + blockIdx.x) * 4096
                                   + hh2 * 1024 + (half2 * 16 + qr) * 32 + qc * 2;
#pragma unroll
                        for (int nt = 0; nt < 4; nt++) {
                            *(float2*)(dst + nt * 8)           = make_float2(co[nt][0], co[nt][1]);
                            *(float2*)(dst + 8 * 32 + nt * 8)  = make_float2(co[nt][2], co[nt][3]);
#pragma unroll
                            for (int z = 0; z < 4; z++) co[nt][z] = 0.f;
                        }
                    }
                    ob = bj;
                }
#pragma unroll
                for (int ks = 0; ks < 4; ks++) {
                    const unsigned off = (unsigned)(ks * 8192);
                    unsigned Ah[4], Al[4], B0h[4], B1h[4], B0l[4], B1l[4];
                    ldsm4t(Ah, aOut + off);
                    ldsm4t(Al, aOut + 32768u + off);
                    ldsm4t(B0h, bOut0 + off);
                    ldsm4t(B1h, bOut1 + off);
                    ldsm4t(B0l, bOut0 + 32768u + off);
                    ldsm4t(B1l, bOut1 + 32768u + off);
                    mma_bf16(co[0], Ah[0], Ah[1], Ah[2], Ah[3], B0h[0], B0h[1]);
                    mma_bf16(co[0], Ah[0], Ah[1], Ah[2], Ah[3], B0l[0], B0l[1]);
                    mma_bf16(co[0], Al[0], Al[1], Al[2], Al[3], B0h[0], B0h[1]);
                    mma_bf16(co[1], Ah[0], Ah[1], Ah[2], Ah[3], B0h[2], B0h[3]);
                    mma_bf16(co[1], Ah[0], Ah[1], Ah[2], Ah[3], B0l[2], B0l[3]);
                    mma_bf16(co[1], Al[0], Al[1], Al[2], Al[3], B0h[2], B0h[3]);
                    mma_bf16(co[2], Ah[0], Ah[1], Ah[2], Ah[3], B1h[0], B1h[1]);
                    mma_bf16(co[2], Ah[0], Ah[1], Ah[2], Ah[3], B1l[0], B1l[1]);
                    mma_bf16(co[2], Al[0], Al[1], Al[2], Al[3], B1h[0], B1h[1]);
                    mma_bf16(co[3], Ah[0], Ah[1], Ah[2], Ah[3], B1h[2], B1h[3]);
                    mma_bf16(co[3], Ah[0], Ah[1], Ah[2], Ah[3], B1l[2], B1l[3]);
                    mma_bf16(co[3], Al[0], Al[1], Al[2], Al[3], B1h[2], B1h[3]);
                }
            }
        }
        __syncthreads();   // bar1: partials visible; outer's kn/vn reads done

        // ================= PHASE B =================
        if (warp < 8) {
            // stats + normalize + store kn/vn (bf16 hi/lo, swizzled)
            const float2* pk = kw ? partk : partv;
#pragma unroll
            for (int mi = 0; mi < 2; mi++) {
#pragma unroll
                for (int half = 0; half < 2; half++) {
                    const int row = m0 + mi * 16 + half * 8 + qr;
                    const float2 p0 = pk[row * 2];
                    const float2 p1 = pk[row * 2 + 1];
                    const float mu = (p0.x + p1.x) * (1.f / 128.f);
                    const float ms = (p0.y + p1.y) * (1.f / 128.f);
                    const float rr = rsqrtf(ms - mu * mu + 1e-5f);
                    const float mm = -mu * rr;
#pragma unroll
                    for (int nj = 0; nj < 8; nj++) {
                        const int ch = (n0g + nj * 8 + qc * 2) & 127;
                        const float2 g0 = gb[ch];
                        const float2 g1 = gb[ch + 1];
                        float& v0 = c[mi][nj][half * 2];
                        float& v1 = c[mi][nj][half * 2 + 1];
                        v0 = fmaf(fmaf(v0, rr, mm), g0.x, g0.y);
                        v1 = fmaf(fmaf(v1, rr, mm), g1.x, g1.y);
                    }
                }
            }
#pragma unroll
            for (int mi = 0; mi < 2; mi++) {
                const int r = m0 + mi * 16 + qr;
#pragma unroll
                for (int nj = 0; nj < 8; nj++) {
                    const int chb = (n0g + nj * 8 + qc * 2) * 2;
                    __nv_bfloat162 h0 = __floats2bfloat162_rn(c[mi][nj][0], c[mi][nj][1]);
                    float2 hf0 = __bfloat1622float2(h0);
                    __nv_bfloat162 l0 = __floats2bfloat162_rn(c[mi][nj][0] - hf0.x,
                                                              c[mi][nj][1] - hf0.y);
                    __nv_bfloat162 h1 = __floats2bfloat162_rn(c[mi][nj][2], c[mi][nj][3]);
                    float2 hf1 = __bfloat1622float2(h1);
                    __nv_bfloat162 l1 = __floats2bfloat162_rn(c[mi][nj][2] - hf1.x,
                                                              c[mi][nj][3] - hf1.y);
                    const unsigned o0 = skvb_off(r,     chb);
                    const unsigned o1 = skvb_off(r + 8, chb);
                    *(__nv_bfloat162*)(kvh + o0) = h0;
                    *(__nv_bfloat162*)(kvl + o0) = l0;
                    *(__nv_bfloat162*)(kvh + o1) = h1;
                    *(__nv_bfloat162*)(kvl + o1) = l1;
                }
            }
        } else {
            // cvt X(i+1) regs -> XT, then prefetch X(i+2) regs
            const int nxt = chunk + NPART;
            if (nxt < NCHUNK1) {
#pragma unroll
                for (int i = 0; i < 8; i++) {
                    const int idx = aux + i * 256;
                    const int row = idx >> 5;
                    const int kb  = (idx & 31) << 3;
                    const float4 x = xr[i];
                    __nv_bfloat162 h0 = __floats2bfloat162_rn(x.x, x.y);
                    __nv_bfloat162 h1 = __floats2bfloat162_rn(x.z, x.w);
                    float2 f0 = __bfloat1622float2(h0);
                    float2 f1 = __bfloat1622float2(h1);
                    __nv_bfloat162 l0 = __floats2bfloat162_rn(x.x - f0.x, x.y - f0.y);
                    __nv_bfloat162 l1 = __floats2bfloat162_rn(x.z - f1.x, x.w - f1.y);
                    const unsigned off = sw_off(row, kb);
                    *(__nv_bfloat162*)(xt + off)             = h0;
                    *(__nv_bfloat162*)(xt + off + 4)         = h1;
                    *(__nv_bfloat162*)(xt + 16384 + off)     = l0;
                    *(__nv_bfloat162*)(xt + 16384 + off + 4) = l1;
                }
                const int nxt2 = nxt + NPART;
                if (nxt2 < NCHUNK1) {
                    const float4* src = (const float4*)X + (size_t)nxt2 * 2048;
#pragma unroll
                    for (int i = 0; i < 8; i++) xr[i] = src[aux + i * 256];
                }
            }
        }
        pend = chunk;
        __syncthreads();   // bar2: kn/vn(i) + XT(i+1) complete
    }

    // Epilogue: aux warps run the outer product for the final chunk + flush
    if (warp >= 8 && pend >= 0) {
        const int bj = pend >> 10;
        if (bj != ob) {
            if (ob >= 0) {
                float* dst = g_part + ((size_t)ob * NPART + blockIdx.x) * 4096
                           + hh2 * 1024 + (half2 * 16 + qr) * 32 + qc * 2;
#pragma unroll
                for (int nt = 0; nt < 4; nt++) {
                    *(float2*)(dst + nt * 8)          = make_float2(co[nt][0], co[nt][1]);
                    *(float2*)(dst + 8 * 32 + nt * 8) = make_float2(co[nt][2], co[nt][3]);
#pragma unroll
                    for (int z = 0; z < 4; z++) co[nt][z] = 0.f;
                }
            }
            ob = bj;
        }
#pragma unroll
        for (int ks = 0; ks < 4; ks++) {
            const unsigned off = (unsigned)(ks * 8192);
            unsigned Ah[4], Al[4], B0h[4], B1h[4], B0l[4], B1l[4];
            ldsm4t(Ah, aOut + off);
            ldsm4t(Al, aOut + 32768u + off);
            ldsm4t(B0h, bOut0 + off);
            ldsm4t(B1h, bOut1 + off);
            ldsm4t(B0l, bOut0 + 32768u + off);
            ldsm4t(B1l, bOut1 + 32768u + off);
            mma_bf16(co[0], Ah[0], Ah[1], Ah[2], Ah[3], B0h[0], B0h[1]);
            mma_bf16(co[0], Ah[0], Ah[1], Ah[2], Ah[3], B0l[0], B0l[1]);
            mma_bf16(co[0], Al[0], Al[1], Al[2], Al[3], B0h[0], B0h[1]);
            mma_bf16(co[1], Ah[0], Ah[1], Ah[2], Ah[3], B0h[2], B0h[3]);
            mma_bf16(co[1], Ah[0], Ah[1], Ah[2], Ah[3], B0l[2], B0l[3]);
            mma_bf16(co[1], Al[0], Al[1], Al[2], Al[3], B0h[2], B0h[3]);
            mma_bf16(co[2], Ah[0], Ah[1], Ah[2], Ah[3], B1h[0], B1h[1]);
            mma_bf16(co[2], Ah[0], Ah[1], Ah[2], Ah[3], B1l[0], B1l[1]);
            mma_bf16(co[2], Al[0], Al[1], Al[2], Al[3], B1h[0], B1h[1]);
            mma_bf16(co[3], Ah[0], Ah[1], Ah[2], Ah[3], B1h[2], B1h[3]);
            mma_bf16(co[3], Ah[0], Ah[1], Ah[2], Ah[3], B1l[2], B1l[3]);
            mma_bf16(co[3], Al[0], Al[1], Al[2], Al[3], B1h[2], B1h[3]);
        }
        float* dst = g_part + ((size_t)ob * NPART + blockIdx.x) * 4096
                   + hh2 * 1024 + (half2 * 16 + qr) * 32 + qc * 2;
#pragma unroll
        for (int nt = 0; nt < 4; nt++) {
            *(float2*)(dst + nt * 8)          = make_float2(co[nt][0], co[nt][1]);
            *(float2*)(dst + 8 * 32 + nt * 8) = make_float2(co[nt][2], co[nt][3]);
        }
    }
}

// ============================================================================
// Kernel 2a: reduce 148 per-CTA partials -> g_kv.
// ============================================================================
__global__ void k2a_reduce()
{
    const int gid = blockIdx.x * 256 + threadIdx.x;
    const int b = gid >> 12;
    const int e = gid & 4095;
    const float* src = g_part + (size_t)b * NPART * 4096 + e;
    float s = 0.f;
#pragma unroll 4
    for (int j = 0; j < NPART; j++) s += src[(size_t)j * 4096];
    g_kv[gid] = s;
}

// ============================================================================
// Kernel 2b: Wq_eff[b][n][c] = (1/N) * sum_d Wq[c][h*32+d] * kv[b][h][d][e]
// ============================================================================
__global__ void k2b_fold(const float* __restrict__ Wq)
{
    const int gid = blockIdx.x * 256 + threadIdx.x;
    const int b  = gid >> 14;
    const int r  = gid & 16383;
    const int cp = r >> 7;
    const int co = r & 127;
    const int e  = co >> 2;
    const int h  = co & 3;
    const float* wq = Wq + cp * 128 + h * 32;
    const float* kv = g_kv + b * 4096 + h * 1024 + e;
    float s = 0.f;
#pragma unroll
    for (int d = 0; d < 32; d++) s += wq[d] * kv[d * 32];
    g_wqeff[b * 16384 + co * 128 + cp] = s * (1.f / 65536.f);
}

// ============================================================================
// Kernel 3 (round-8 version, best known): out = X @ Wq_eff[b]^T (bf16x3)
// ============================================================================
#define K3S_W_HI 0
#define K3S_W_LO 32768
#define K3S_X_HI 65536
#define K3S_X_LO 98304
#define K3S_RAW  131072
#define K3_SMEM  196608

__device__ __forceinline__ void cvt_tile512(const float* __restrict__ src,
                                            char* hi_base, char* lo_base, int tid) {
#pragma unroll
    for (int i = 0; i < 8; i++) {
        const int idx = tid + i * 512;
        const int row = idx >> 5;
        const int kb  = (idx & 31) << 3;
        const float4 x = *(const float4*)(src + idx * 4);
        __nv_bfloat162 h0 = __floats2bfloat162_rn(x.x, x.y);
        __nv_bfloat162 h1 = __floats2bfloat162_rn(x.z, x.w);
        float2 f0 = __bfloat1622float2(h0);
        float2 f1 = __bfloat1622float2(h1);
        __nv_bfloat162 l0 = __floats2bfloat162_rn(x.x - f0.x, x.y - f0.y);
        __nv_bfloat162 l1 = __floats2bfloat162_rn(x.z - f1.x, x.w - f1.y);
        const unsigned off = sw_off(row, kb);
        *(__nv_bfloat162*)(hi_base + off)     = h0;
        *(__nv_bfloat162*)(hi_base + off + 4) = h1;
        *(__nv_bfloat162*)(lo_base + off)     = l0;
        *(__nv_bfloat162*)(lo_base + off + 4) = l1;
    }
}

__device__ __forceinline__ void cvt_w512(const float* __restrict__ src,
                                         char* hi_base, char* lo_base, int tid) {
    if (tid < 256) {
#pragma unroll
        for (int i = 0; i < 16; i++) {
            const int idx = tid + i * 256;
            const int row = idx >> 5;
            const int kb  = (idx & 31) << 3;
            const float4 x = *(const float4*)(src + idx * 4);
            __nv_bfloat162 h0 = __floats2bfloat162_rn(x.x, x.y);
            __nv_bfloat162 h1 = __floats2bfloat162_rn(x.z, x.w);
            float2 f0 = __bfloat1622float2(h0);
            float2 f1 = __bfloat1622float2(h1);
            __nv_bfloat162 l0 = __floats2bfloat162_rn(x.x - f0.x, x.y - f0.y);
            __nv_bfloat162 l1 = __floats2bfloat162_rn(x.z - f1.x, x.w - f1.y);
            const unsigned off = sw_off(row, kb);
            *(__nv_bfloat162*)(hi_base + off)     = h0;
            *(__nv_bfloat162*)(hi_base + off + 4) = h1;
            *(__nv_bfloat162*)(lo_base + off)     = l0;
            *(__nv_bfloat162*)(lo_base + off + 4) = l1;
        }
    }
}

__global__ void __launch_bounds__(512, 1)
k3_out_mma(const float* __restrict__ X, float* __restrict__ out)
{
    extern __shared__ char smem[];
    const int tid  = threadIdx.x;
    const int lane = tid & 31;
    const int warp = tid >> 5;

    const int m0 = (warp & 3) * 32;
    const int n0 = (warp >> 2) * 32;
    const int qr = lane >> 2;
    const int qc = lane & 3;

    float* raw = (float*)(smem + K3S_RAW);

    const unsigned xh_u = (unsigned)__cvta_generic_to_shared(smem + K3S_X_HI);
    const unsigned wh_u = (unsigned)__cvta_generic_to_shared(smem + K3S_W_HI);

    const int laneK = lane & 16;
    const int bKoff = (lane & 8) << 1;
    unsigned aBase[2], aSw[2], bBase[2], bSw[2];
#pragma unroll
    for (int mi = 0; mi < 2; mi++) {
        const int row = m0 + mi * 16 + (lane & 15);
        aSw[mi] = (unsigned)((row & 7) << 4);
        aBase[mi] = xh_u + row * 256;
    }
#pragma unroll
    for (int p = 0; p < 2; p++) {
        const int row = n0 + p * 16 + ((lane >> 1) & 8) + (lane & 7);
        bSw[p] = (unsigned)((row & 7) << 4);
        bBase[p] = wh_u + row * 256;
    }

    {
        const float* src = X + (size_t)blockIdx.x * 16384;
#pragma unroll
        for (int i = 0; i < 8; i++)
            cp16(raw + (tid + i * 512) * 4, src + (tid + i * 512) * 4);
        cp_commit();
    }

    int cur_b = -1;
    for (int chunk = blockIdx.x; chunk < NCHUNK3; chunk += NPART) {
        const int b = chunk >> 9;

        cp_wait_all();
        __syncthreads();

        if (b != cur_b) {
            cvt_w512(g_wqeff + b * 16384, smem + K3S_W_HI, smem + K3S_W_LO, tid);
            cur_b = b;
        }
        cvt_tile512(raw, smem + K3S_X_HI, smem + K3S_X_LO, tid);
        __syncthreads();

        {
            const int nxt = chunk + NPART;
            if (nxt < NCHUNK3) {
                const float* src = X + (size_t)nxt * 16384;
#pragma unroll
                for (int i = 0; i < 8; i++)
                    cp16(raw + (tid + i * 512) * 4, src + (tid + i * 512) * 4);
                cp_commit();
            }
        }

        float c[2][4][4];
#pragma unroll
        for (int mi = 0; mi < 2; mi++)
#pragma unroll
            for (int nj = 0; nj < 4; nj++)
#pragma unroll
                for (int z = 0; z < 4; z++) c[mi][nj][z] = 0.f;

#pragma unroll
        for (int ks = 0; ks < 8; ks++) {
            const int kb = ks * 32;
            unsigned ah[2][4], al[2][4], bh[4][2], bl[4][2];
#pragma unroll
            for (int mi = 0; mi < 2; mi++) {
                const unsigned off = (unsigned)(kb + laneK) ^ aSw[mi];
                ldsm4(ah[mi], aBase[mi] + off);
                ldsm4(al[mi], aBase[mi] + 32768u + off);
            }
#pragma unroll
            for (int p = 0; p < 2; p++) {
                const unsigned off = (unsigned)(kb + bKoff) ^ bSw[p];
                unsigned t[4];
                ldsm4(t, bBase[p] + off);
                bh[2 * p][0] = t[0]; bh[2 * p][1] = t[1];
                bh[2 * p + 1][0] = t[2]; bh[2 * p + 1][1] = t[3];
                ldsm4(t, bBase[p] + 32768u + off);
                bl[2 * p][0] = t[0]; bl[2 * p][1] = t[1];
                bl[2 * p + 1][0] = t[2]; bl[2 * p + 1][1] = t[3];
            }
#pragma unroll
            for (int mi = 0; mi < 2; mi++)
#pragma unroll
                for (int nj = 0; nj < 4; nj++) {
                    mma_bf16(c[mi][nj], ah[mi][0], ah[mi][1], ah[mi][2], ah[mi][3],
                             bh[nj][0], bh[nj][1]);
                    mma_bf16(c[mi][nj], ah[mi][0], ah[mi][1], ah[mi][2], ah[mi][3],
                             bl[nj][0], bl[nj][1]);
                    mma_bf16(c[mi][nj], al[mi][0], al[mi][1], al[mi][2], al[mi][3],
                             bh[nj][0], bh[nj][1]);
                }
        }

        float* obase = out + (size_t)chunk * 16384;
#pragma unroll
        for (int mi = 0; mi < 2; mi++) {
            const int r = m0 + mi * 16 + qr;
#pragma unroll
            for (int nj = 0; nj < 4; nj++) {
                const int col = n0 + nj * 8 + qc * 2;
                *(float2*)(obase + r * 128 + col) =
                    make_float2(c[mi][nj][0], c[mi][nj][1]);
                *(float2*)(obase + (r + 8) * 128 + col) =
                    make_float2(c[mi][nj][2], c[mi][nj][3]);
            }
        }
    }
}

// ============================================================================
extern "C" void kernel_launch(void* const* d_in, const int* in_sizes, int n_in,
                              void* d_out, int out_size)
{
    (void)in_sizes; (void)n_in; (void)out_size;
    const float* X     = (const float*)d_in[0];
    const float* Wq    = (const float*)d_in[1];
    const float* Wk    = (const float*)d_in[2];
    const float* Wv    = (const float*)d_in[3];
    const float* gamma = (const float*)d_in[4];
    const float* beta  = (const float*)d_in[5];
    float* out = (float*)d_out;

    cudaFuncSetAttribute(k1_kv_mma, cudaFuncAttributeMaxDynamicSharedMemorySize,
                         K1_SMEM);    // 227 KB
    cudaFuncSetAttribute(k3_out_mma, cudaFuncAttributeMaxDynamicSharedMemorySize,
                         K3_SMEM);    // 192 KB

    k1_kv_mma<<<NPART, 512, K1_SMEM>>>(X, Wk, Wv, gamma, beta);
    k2a_reduce<<<64, 256>>>();
    k2b_fold<<<256, 256>>>(Wq);
    k3_out_mma<<<NPART, 512, K3_SMEM>>>(X, out);
}